// round 5
// baseline (speedup 1.0000x reference)
#include <cuda_runtime.h>
#include <cstddef>

#define NN 100000
#define NE 3200000
#define HD 256

// ---------------- device scratch (static; no allocations allowed) ----------------
__device__ int   g_rowptr[NN + 1];
__device__ int   g_cursor[NN];
__device__ int   g_col[NE];
__device__ float g_z0[(size_t)NN * HD];
__device__ float g_z1[(size_t)NN * HD];
__device__ float g_hb[(size_t)NN * HD];
__device__ float g_s[HD];
__device__ float g_t[HD];

// ---------------- CSR build ----------------
__global__ void k_zero_deg() {
    int i = blockIdx.x * blockDim.x + threadIdx.x;
    if (i < NN) g_cursor[i] = 0;
}

// dst must point at edge_index row 1 (the destination nodes)
__global__ void k_count(const int* __restrict__ dst) {
    int e = blockIdx.x * blockDim.x + threadIdx.x;
    if (e < NE) atomicAdd(&g_cursor[dst[e]], 1);
}

// single-block chunked exclusive scan: g_rowptr[i] = sum_{j<i} deg[j]
__global__ void k_scan() {
    __shared__ int wsum[32];
    __shared__ int s_carry;
    int tid = threadIdx.x, lane = tid & 31, wid = tid >> 5;
    if (tid == 0) s_carry = 0;
    __syncthreads();
    for (int base = 0; base < NN; base += 1024) {
        int i = base + tid;
        int v = (i < NN) ? g_cursor[i] : 0;
        int x = v;
#pragma unroll
        for (int off = 1; off < 32; off <<= 1) {
            int y = __shfl_up_sync(0xffffffffu, x, off);
            if (lane >= off) x += y;
        }
        if (lane == 31) wsum[wid] = x;
        __syncthreads();
        if (wid == 0) {
            int w = wsum[lane];
#pragma unroll
            for (int off = 1; off < 32; off <<= 1) {
                int y = __shfl_up_sync(0xffffffffu, w, off);
                if (lane >= off) w += y;
            }
            wsum[lane] = w;
        }
        __syncthreads();
        int incl = x + (wid ? wsum[wid - 1] : 0) + s_carry;
        if (i < NN) g_rowptr[i + 1] = incl;
        __syncthreads();
        if (tid == 1023) s_carry = incl;
        __syncthreads();
    }
    if (tid == 0) g_rowptr[0] = 0;
}

__global__ void k_init_cursor() {
    int i = blockIdx.x * blockDim.x + threadIdx.x;
    if (i < NN) g_cursor[i] = g_rowptr[i];
}

__global__ void k_fill(const int* __restrict__ ei) {
    int e = blockIdx.x * blockDim.x + threadIdx.x;
    if (e < NE) {
        int s = ei[e];          // src = edge_index[0][e]
        int d = ei[NE + e];     // dst = edge_index[1][e]
        int p = atomicAdd(&g_cursor[d], 1);
        g_col[p] = s;
    }
}

// ---------------- aggregation: out[i] = h[i] + sum_{j in N(i)} h[j], warp per node ----------------
template <int F>
__global__ void k_agg(const float* __restrict__ h, float* __restrict__ out) {
    int w = (blockIdx.x * blockDim.x + threadIdx.x) >> 5;
    if (w >= NN) return;
    int lane = threadIdx.x & 31;
    constexpr int V = F / 128;  // float4 chunks per lane (1 or 2)
    const float4* hv = (const float4*)h;
    float4 acc[V];
#pragma unroll
    for (int v = 0; v < V; v++) acc[v] = hv[(size_t)w * (F / 4) + v * 32 + lane];
    int e = g_rowptr[w], end = g_rowptr[w + 1];
    for (; e + 1 < end; e += 2) {
        int s0 = g_col[e], s1 = g_col[e + 1];
        const float4* p0 = hv + (size_t)s0 * (F / 4);
        const float4* p1 = hv + (size_t)s1 * (F / 4);
        float4 t0[V], t1[V];
#pragma unroll
        for (int v = 0; v < V; v++) {
            t0[v] = __ldg(p0 + v * 32 + lane);
            t1[v] = __ldg(p1 + v * 32 + lane);
        }
#pragma unroll
        for (int v = 0; v < V; v++) {
            acc[v].x += t0[v].x + t1[v].x;
            acc[v].y += t0[v].y + t1[v].y;
            acc[v].z += t0[v].z + t1[v].z;
            acc[v].w += t0[v].w + t1[v].w;
        }
    }
    if (e < end) {
        int s0 = g_col[e];
        const float4* p0 = hv + (size_t)s0 * (F / 4);
#pragma unroll
        for (int v = 0; v < V; v++) {
            float4 t0 = __ldg(p0 + v * 32 + lane);
            acc[v].x += t0.x; acc[v].y += t0.y; acc[v].z += t0.z; acc[v].w += t0.w;
        }
    }
    float4* ov = (float4*)out;
#pragma unroll
    for (int v = 0; v < V; v++) ov[(size_t)w * (F / 4) + v * 32 + lane] = acc[v];
}

// ---------------- BN fold: s = g*rsqrt(var+eps); t = (b1-mu)*s + be ----------------
__global__ void k_bnfold(const float* __restrict__ g, const float* __restrict__ be,
                         const float* __restrict__ mu, const float* __restrict__ var,
                         const float* __restrict__ b1) {
    int j = threadIdx.x;
    float s = g[j] * rsqrtf(var[j] + 1e-5f);
    g_s[j] = s;
    g_t[j] = (b1[j] - mu[j]) * s + be[j];
}

// ---------------- fp32 GEMM with packed f32x2 FMA; C[M x 256] = A[M x K] @ W[K x 256] ----------------
__device__ __forceinline__ unsigned long long pk2(float x, float y) {
    unsigned long long r;
    asm("mov.b64 %0,{%1,%2};" : "=l"(r) : "f"(x), "f"(y));
    return r;
}
__device__ __forceinline__ void upk2(unsigned long long v, float& x, float& y) {
    asm("mov.b64 {%0,%1},%2;" : "=f"(x), "=f"(y) : "l"(v));
}
#define FFMA2(c, a, b) asm("fma.rn.f32x2 %0,%1,%2,%0;" : "+l"(c) : "l"(a), "l"(b))

// mode 0: relu(acc*sc[c]+sh[c]); mode 1: relu(acc+sh[c]); mode 2: acc+sh[c]
__global__ __launch_bounds__(256, 2) void k_gemm(const float* __restrict__ A,
                                                 const float* __restrict__ W,
                                                 float* __restrict__ C, int M, int K,
                                                 const float* __restrict__ sc,
                                                 const float* __restrict__ sh, int mode) {
    __shared__ float As[16][128];
    __shared__ float Ws[16][128];
    int tid = threadIdx.x;
    int bm = blockIdx.x, bn = blockIdx.y;
    int tx = tid & 15, ty = tid >> 4;

    unsigned long long acc[8][4];
#pragma unroll
    for (int i = 0; i < 8; i++)
#pragma unroll
        for (int j = 0; j < 4; j++) acc[i][j] = 0ULL;

    int ar = tid >> 1;          // 0..127 (A tile row)
    int ac = (tid & 1) * 8;     // 0 or 8 (A tile col base)
    int wr = tid >> 4;          // 0..15  (W tile row)
    int wc4 = tid & 15;         // W float4 col
    int rowg = bm * 128 + ar;

    for (int kt = 0; kt < K; kt += 16) {
        float4 a0, a1;
        if (rowg < M) {
            const float4* ap = (const float4*)(A + (size_t)rowg * K + kt + ac);
            a0 = ap[0];
            a1 = ap[1];
        } else {
            a0 = make_float4(0.f, 0.f, 0.f, 0.f);
            a1 = a0;
        }
        As[ac + 0][ar] = a0.x; As[ac + 1][ar] = a0.y;
        As[ac + 2][ar] = a0.z; As[ac + 3][ar] = a0.w;
        As[ac + 4][ar] = a1.x; As[ac + 5][ar] = a1.y;
        As[ac + 6][ar] = a1.z; As[ac + 7][ar] = a1.w;

        const float4* wp = (const float4*)(W + (size_t)(kt + wr) * 256 + bn * 128);
        ((float4*)Ws[wr])[wc4] = wp[wc4];
        ((float4*)Ws[wr])[wc4 + 16] = wp[wc4 + 16];
        __syncthreads();

#pragma unroll
        for (int k = 0; k < 16; k++) {
            float4 af0 = *(const float4*)&As[k][ty * 8];
            float4 af1 = *(const float4*)&As[k][ty * 8 + 4];
            ulonglong2 b0 = *(const ulonglong2*)&Ws[k][tx * 8];
            ulonglong2 b1 = *(const ulonglong2*)&Ws[k][tx * 8 + 4];
            unsigned long long ap8[8];
            ap8[0] = pk2(af0.x, af0.x); ap8[1] = pk2(af0.y, af0.y);
            ap8[2] = pk2(af0.z, af0.z); ap8[3] = pk2(af0.w, af0.w);
            ap8[4] = pk2(af1.x, af1.x); ap8[5] = pk2(af1.y, af1.y);
            ap8[6] = pk2(af1.z, af1.z); ap8[7] = pk2(af1.w, af1.w);
            unsigned long long bb[4] = {b0.x, b0.y, b1.x, b1.y};
#pragma unroll
            for (int i = 0; i < 8; i++)
#pragma unroll
                for (int j = 0; j < 4; j++) FFMA2(acc[i][j], ap8[i], bb[j]);
        }
        __syncthreads();
    }

    // epilogue
    int cb = bn * 128 + tx * 8;
    float scv[8], shv[8];
#pragma unroll
    for (int j = 0; j < 8; j++) {
        shv[j] = sh[cb + j];
        scv[j] = (mode == 0) ? sc[cb + j] : 1.0f;
    }
#pragma unroll
    for (int i = 0; i < 8; i++) {
        int r = bm * 128 + ty * 8 + i;
        if (r >= M) continue;
        float o[8];
#pragma unroll
        for (int j = 0; j < 4; j++) upk2(acc[i][j], o[2 * j], o[2 * j + 1]);
#pragma unroll
        for (int j = 0; j < 8; j++) {
            float v = o[j] * scv[j] + shv[j];
            if (mode != 2) v = fmaxf(v, 0.f);
            o[j] = v;
        }
        *(float4*)&C[(size_t)r * 256 + cb] = make_float4(o[0], o[1], o[2], o[3]);
        *(float4*)&C[(size_t)r * 256 + cb + 4] = make_float4(o[4], o[5], o[6], o[7]);
    }
}

// ---------------- final projection: out[i] = h[i] @ W[256x2] + b, warp per node ----------------
__global__ void k_out(const float* __restrict__ h, const float* __restrict__ W,
                      const float* __restrict__ b, float* __restrict__ out) {
    __shared__ float Ws[512];
    int tid = threadIdx.x;
    Ws[tid] = W[tid];
    Ws[tid + 256] = W[tid + 256];
    __syncthreads();
    int w = (blockIdx.x * blockDim.x + tid) >> 5;
    if (w >= NN) return;
    int lane = tid & 31;
    const float4* hv = (const float4*)(h + (size_t)w * 256);
    float a0 = 0.f, a1 = 0.f;
#pragma unroll
    for (int v = 0; v < 2; v++) {
        float4 t = hv[v * 32 + lane];
        int k = (v * 32 + lane) * 4;
        a0 += t.x * Ws[(k + 0) * 2] + t.y * Ws[(k + 1) * 2] + t.z * Ws[(k + 2) * 2] + t.w * Ws[(k + 3) * 2];
        a1 += t.x * Ws[(k + 0) * 2 + 1] + t.y * Ws[(k + 1) * 2 + 1] + t.z * Ws[(k + 2) * 2 + 1] + t.w * Ws[(k + 3) * 2 + 1];
    }
#pragma unroll
    for (int off = 16; off > 0; off >>= 1) {
        a0 += __shfl_down_sync(0xffffffffu, a0, off);
        a1 += __shfl_down_sync(0xffffffffu, a1, off);
    }
    if (lane == 0) {
        out[(size_t)w * 2 + 0] = a0 + b[0];
        out[(size_t)w * 2 + 1] = a1 + b[1];
    }
}

// ---------------- host ----------------
extern "C" void kernel_launch(void* const* d_in, const int* in_sizes, int n_in,
                              void* d_out, int out_size) {
    const float* x = (const float*)d_in[0];
    const int* ei = (const int*)d_in[1];
    const float* outW = (const float*)d_in[26];
    const float* outB = (const float*)d_in[27];
    auto L = [&](int l, int p) { return (const float*)d_in[2 + l * 8 + p]; };
    // params per layer: 0=W1 1=b1 2=g 3=be 4=mu 5=var 6=W2 7=b2

    float *z0, *z1, *hb;
    cudaGetSymbolAddress((void**)&z0, g_z0);
    cudaGetSymbolAddress((void**)&z1, g_z1);
    cudaGetSymbolAddress((void**)&hb, g_hb);
    float *sp, *tp;
    cudaGetSymbolAddress((void**)&sp, g_s);
    cudaGetSymbolAddress((void**)&tp, g_t);

    // CSR build (shared by all 3 layers) — histogram over DST row (ei + NE)
    k_zero_deg<<<(NN + 255) / 256, 256>>>();
    k_count<<<(NE + 255) / 256, 256>>>(ei + NE);
    k_scan<<<1, 1024>>>();
    k_init_cursor<<<(NN + 255) / 256, 256>>>();
    k_fill<<<(NE + 255) / 256, 256>>>(ei);

    dim3 gg(782, 2);
    int aggBlocks = (NN + 7) / 8;  // 8 warps (nodes) per 256-thread block

    // Layer 1 (F=128)
    k_agg<128><<<aggBlocks, 256>>>(x, z0);
    k_bnfold<<<1, 256>>>(L(0, 2), L(0, 3), L(0, 4), L(0, 5), L(0, 1));
    k_gemm<<<gg, 256>>>(z0, L(0, 0), z1, NN, 128, sp, tp, 0);
    k_gemm<<<gg, 256>>>(z1, L(0, 6), hb, NN, 256, nullptr, L(0, 7), 1);

    // Layer 2
    k_agg<256><<<aggBlocks, 256>>>(hb, z0);
    k_bnfold<<<1, 256>>>(L(1, 2), L(1, 3), L(1, 4), L(1, 5), L(1, 1));
    k_gemm<<<gg, 256>>>(z0, L(1, 0), z1, NN, 256, sp, tp, 0);
    k_gemm<<<gg, 256>>>(z1, L(1, 6), hb, NN, 256, nullptr, L(1, 7), 1);

    // Layer 3 (no final relu)
    k_agg<256><<<aggBlocks, 256>>>(hb, z0);
    k_bnfold<<<1, 256>>>(L(2, 2), L(2, 3), L(2, 4), L(2, 5), L(2, 1));
    k_gemm<<<gg, 256>>>(z0, L(2, 0), z1, NN, 256, sp, tp, 0);
    k_gemm<<<gg, 256>>>(z1, L(2, 6), hb, NN, 256, nullptr, L(2, 7), 2);

    // Output projection
    k_out<<<aggBlocks, 256>>>(hb, outW, outB, (float*)d_out);
}

// round 7
// speedup vs baseline: 1.0915x; 1.0915x over previous
#include <cuda_runtime.h>
#include <cuda_bf16.h>
#include <mma.h>
#include <cstdint>
#include <cstddef>

using namespace nvcuda;

#define NN 100000
#define NE 3200000
#define HD 256

// ---------------- device scratch (static; no allocations allowed) ----------------
__device__ int   g_rowptr[NN + 1];
__device__ int   g_cursor[NN];
__device__ int   g_col[NE];
__device__ float g_z0[(size_t)NN * HD];
__device__ float g_z1[(size_t)NN * HD];
__device__ float g_hb[(size_t)NN * HD];
__device__ float g_s[HD];
__device__ float g_t[HD];
// bf16 weight images, plain row-major [K][256]
__device__ __nv_bfloat16 g_wh[256 * 256];
__device__ __nv_bfloat16 g_wl[256 * 256];

// ---------------- CSR build ----------------
__global__ void k_zero_deg() {
    int i = blockIdx.x * blockDim.x + threadIdx.x;
    if (i < NN) g_cursor[i] = 0;
}
__global__ void k_count(const int* __restrict__ dst) {
    int e = blockIdx.x * blockDim.x + threadIdx.x;
    if (e < NE) atomicAdd(&g_cursor[dst[e]], 1);
}
__global__ void k_scan() {
    __shared__ int wsum[32];
    __shared__ int s_carry;
    int tid = threadIdx.x, lane = tid & 31, wid = tid >> 5;
    if (tid == 0) s_carry = 0;
    __syncthreads();
    for (int base = 0; base < NN; base += 1024) {
        int i = base + tid;
        int v = (i < NN) ? g_cursor[i] : 0;
        int x = v;
#pragma unroll
        for (int off = 1; off < 32; off <<= 1) {
            int y = __shfl_up_sync(0xffffffffu, x, off);
            if (lane >= off) x += y;
        }
        if (lane == 31) wsum[wid] = x;
        __syncthreads();
        if (wid == 0) {
            int w = wsum[lane];
#pragma unroll
            for (int off = 1; off < 32; off <<= 1) {
                int y = __shfl_up_sync(0xffffffffu, w, off);
                if (lane >= off) w += y;
            }
            wsum[lane] = w;
        }
        __syncthreads();
        int incl = x + (wid ? wsum[wid - 1] : 0) + s_carry;
        if (i < NN) g_rowptr[i + 1] = incl;
        __syncthreads();
        if (tid == 1023) s_carry = incl;
        __syncthreads();
    }
    if (tid == 0) g_rowptr[0] = 0;
}
__global__ void k_init_cursor() {
    int i = blockIdx.x * blockDim.x + threadIdx.x;
    if (i < NN) g_cursor[i] = g_rowptr[i];
}
__global__ void k_fill(const int* __restrict__ ei) {
    int e = blockIdx.x * blockDim.x + threadIdx.x;
    if (e < NE) {
        int s = ei[e];
        int d = ei[NE + e];
        int p = atomicAdd(&g_cursor[d], 1);
        g_col[p] = s;
    }
}

// ---------------- aggregation: out[i] = h[i] + sum_{j in N(i)} h[j], warp per node ----------------
template <int F>
__global__ void k_agg(const float* __restrict__ h, float* __restrict__ out) {
    int w = (blockIdx.x * blockDim.x + threadIdx.x) >> 5;
    if (w >= NN) return;
    int lane = threadIdx.x & 31;
    constexpr int V = F / 128;
    const float4* hv = (const float4*)h;
    float4 acc[V];
#pragma unroll
    for (int v = 0; v < V; v++) acc[v] = hv[(size_t)w * (F / 4) + v * 32 + lane];
    int e = g_rowptr[w], end = g_rowptr[w + 1];
    for (; e + 1 < end; e += 2) {
        int s0 = g_col[e], s1 = g_col[e + 1];
        const float4* p0 = hv + (size_t)s0 * (F / 4);
        const float4* p1 = hv + (size_t)s1 * (F / 4);
        float4 t0[V], t1[V];
#pragma unroll
        for (int v = 0; v < V; v++) {
            t0[v] = __ldg(p0 + v * 32 + lane);
            t1[v] = __ldg(p1 + v * 32 + lane);
        }
#pragma unroll
        for (int v = 0; v < V; v++) {
            acc[v].x += t0[v].x + t1[v].x;
            acc[v].y += t0[v].y + t1[v].y;
            acc[v].z += t0[v].z + t1[v].z;
            acc[v].w += t0[v].w + t1[v].w;
        }
    }
    if (e < end) {
        int s0 = g_col[e];
        const float4* p0 = hv + (size_t)s0 * (F / 4);
#pragma unroll
        for (int v = 0; v < V; v++) {
            float4 t0 = __ldg(p0 + v * 32 + lane);
            acc[v].x += t0.x; acc[v].y += t0.y; acc[v].z += t0.z; acc[v].w += t0.w;
        }
    }
    float4* ov = (float4*)out;
#pragma unroll
    for (int v = 0; v < V; v++) ov[(size_t)w * (F / 4) + v * 32 + lane] = acc[v];
}

// ---------------- BN fold ----------------
__global__ void k_bnfold(const float* __restrict__ g, const float* __restrict__ be,
                         const float* __restrict__ mu, const float* __restrict__ var,
                         const float* __restrict__ b1) {
    int j = threadIdx.x;
    float s = g[j] * rsqrtf(var[j] + 1e-5f);
    g_s[j] = s;
    g_t[j] = (b1[j] - mu[j]) * s + be[j];
}

// ---------------- weight convert: W[K][256] fp32 -> bf16 hi/lo row-major images ----------------
__global__ void k_wconv(const float* __restrict__ W) {
    int k = blockIdx.x;
    int n = threadIdx.x;
    float v = W[k * 256 + n];
    __nv_bfloat16 h = __float2bfloat16(v);
    __nv_bfloat16 l = __float2bfloat16(v - __bfloat162float(h));
    g_wh[k * 256 + n] = h;
    g_wl[k * 256 + n] = l;
}

// ---------------- wmma split-bf16 GEMM: C[M x 256] = A[M x K] @ W[K x 256], fused BN/ReLU ----------------
// CTA tile 128x128, grid (ceil(M/128), 2). 8 warps in 4x2; warp tile 32x64.
// K-chunk = 32. smem: A_hi/A_lo [128 x 32] (ld 40), B_hi/B_lo [32 x 128] (ld 136),
// C tile [128 x 136] fp32 overlays the A/B region after the k-loop.
#define ALD 40
#define BLD 136
#define SM_AH 0
#define SM_AL (128 * ALD * 2)                 // 10240
#define SM_BH (SM_AL + 128 * ALD * 2)         // 20480
#define SM_BL (SM_BH + 32 * BLD * 2)          // 29184
#define SM_BYTES (128 * BLD * 4)              // 69632 (C tile dominates)

__global__ __launch_bounds__(256, 1) void k_mgemm(
    const float* __restrict__ A, float* __restrict__ C, int M, int K,
    const float* __restrict__ sc, const float* __restrict__ sh, int mode) {
    extern __shared__ char sm[];
    __nv_bfloat16* AH = (__nv_bfloat16*)(sm + SM_AH);
    __nv_bfloat16* AL = (__nv_bfloat16*)(sm + SM_AL);
    __nv_bfloat16* BH = (__nv_bfloat16*)(sm + SM_BH);
    __nv_bfloat16* BL = (__nv_bfloat16*)(sm + SM_BL);
    float* Cs = (float*)sm;

    int tid = threadIdx.x, wid = tid >> 5;
    int bm = blockIdx.x, bn = blockIdx.y;
    int moff = (wid & 3) * 32;   // warp m offset in tile
    int noff = (wid >> 2) * 64;  // warp n offset in tile

    wmma::fragment<wmma::accumulator, 16, 16, 16, float> acc[2][4];
#pragma unroll
    for (int mf = 0; mf < 2; mf++)
#pragma unroll
        for (int nf = 0; nf < 4; nf++) wmma::fill_fragment(acc[mf][nf], 0.0f);

    for (int kt = 0; kt < K; kt += 32) {
        __syncthreads();  // previous iteration's reads done before overwrite

        // ---- A chunk: 128 rows x 32 k fp32 -> bf16 hi/lo ----
#pragma unroll
        for (int i = 0; i < 4; i++) {
            int f = tid + i * 256;     // float4 id 0..1023
            int row = f >> 3;          // 8 float4 per row
            int k0 = (f & 7) * 4;
            int rg = bm * 128 + row;
            float4 v = (rg < M) ? *(const float4*)(A + (size_t)rg * K + kt + k0)
                                : make_float4(0.f, 0.f, 0.f, 0.f);
            float av[4] = {v.x, v.y, v.z, v.w};
            uint32_t hp[2], lp[2];
#pragma unroll
            for (int p = 0; p < 2; p++) {
                __nv_bfloat16 h0 = __float2bfloat16(av[2 * p]);
                __nv_bfloat16 h1 = __float2bfloat16(av[2 * p + 1]);
                __nv_bfloat16 l0 = __float2bfloat16(av[2 * p] - __bfloat162float(h0));
                __nv_bfloat16 l1 = __float2bfloat16(av[2 * p + 1] - __bfloat162float(h1));
                hp[p] = (uint32_t)__bfloat16_as_ushort(h0) | ((uint32_t)__bfloat16_as_ushort(h1) << 16);
                lp[p] = (uint32_t)__bfloat16_as_ushort(l0) | ((uint32_t)__bfloat16_as_ushort(l1) << 16);
            }
            int el = row * ALD + k0;   // element offset; (2*el) % 8 == 0
            *(uint2*)((char*)AH + 2 * el) = make_uint2(hp[0], hp[1]);
            *(uint2*)((char*)AL + 2 * el) = make_uint2(lp[0], lp[1]);
        }

        // ---- B chunk: 32 k-rows x 128 cols bf16 from preconverted images ----
#pragma unroll
        for (int i = 0; i < 2; i++) {
            int j = tid + i * 256;     // uint4 id 0..511 (8 bf16 each)
            int r = j >> 4;            // 16 uint4 per row
            int cc = (j & 15) * 8;
            const uint4* srcH = (const uint4*)(g_wh + (size_t)(kt + r) * 256 + bn * 128 + cc);
            const uint4* srcL = (const uint4*)(g_wl + (size_t)(kt + r) * 256 + bn * 128 + cc);
            int el = r * BLD + cc;     // (2*el) % 16 == 0
            *(uint4*)((char*)BH + 2 * el) = __ldg(srcH);
            *(uint4*)((char*)BL + 2 * el) = __ldg(srcL);
        }
        __syncthreads();

        // ---- 2 x k16 wmma steps, 3 passes ----
#pragma unroll
        for (int kk = 0; kk < 32; kk += 16) {
            wmma::fragment<wmma::matrix_a, 16, 16, 16, __nv_bfloat16, wmma::row_major> ah[2], al[2];
            wmma::fragment<wmma::matrix_b, 16, 16, 16, __nv_bfloat16, wmma::row_major> bh[4], bl[4];
#pragma unroll
            for (int mf = 0; mf < 2; mf++) {
                const __nv_bfloat16* pa = AH + (moff + mf * 16) * ALD + kk;
                const __nv_bfloat16* pl = AL + (moff + mf * 16) * ALD + kk;
                wmma::load_matrix_sync(ah[mf], pa, ALD);
                wmma::load_matrix_sync(al[mf], pl, ALD);
            }
#pragma unroll
            for (int nf = 0; nf < 4; nf++) {
                const __nv_bfloat16* pb = BH + kk * BLD + noff + nf * 16;
                const __nv_bfloat16* pbl = BL + kk * BLD + noff + nf * 16;
                wmma::load_matrix_sync(bh[nf], pb, BLD);
                wmma::load_matrix_sync(bl[nf], pbl, BLD);
            }
#pragma unroll
            for (int mf = 0; mf < 2; mf++)
#pragma unroll
                for (int nf = 0; nf < 4; nf++) {
                    wmma::mma_sync(acc[mf][nf], ah[mf], bh[nf], acc[mf][nf]);
                    wmma::mma_sync(acc[mf][nf], ah[mf], bl[nf], acc[mf][nf]);
                    wmma::mma_sync(acc[mf][nf], al[mf], bh[nf], acc[mf][nf]);
                }
        }
    }

    __syncthreads();  // all smem A/B reads done; reuse as C tile
#pragma unroll
    for (int mf = 0; mf < 2; mf++)
#pragma unroll
        for (int nf = 0; nf < 4; nf++)
            wmma::store_matrix_sync(Cs + (moff + mf * 16) * BLD + noff + nf * 16,
                                    acc[mf][nf], BLD, wmma::mem_row_major);
    __syncthreads();

    // ---- write out with fused BN/bias/ReLU ----
    // mode 0: relu(v*sc+sh); 1: relu(v+sh); 2: v+sh
    int row = tid >> 1;
    int cs = (tid & 1) * 64;
    int rg = bm * 128 + row;
    if (rg < M) {
#pragma unroll
        for (int q = 0; q < 16; q++) {
            int c = cs + q * 4;
            float4 v = *(float4*)(Cs + row * BLD + c);
            int gc = bn * 128 + c;
            float o[4] = {v.x, v.y, v.z, v.w};
#pragma unroll
            for (int j = 0; j < 4; j++) {
                float r;
                if (mode == 0) r = o[j] * __ldg(sc + gc + j) + __ldg(sh + gc + j);
                else r = o[j] + __ldg(sh + gc + j);
                if (mode != 2) r = fmaxf(r, 0.f);
                o[j] = r;
            }
            *(float4*)(C + (size_t)rg * 256 + gc) = make_float4(o[0], o[1], o[2], o[3]);
        }
    }
}

// ---------------- final projection ----------------
__global__ void k_out(const float* __restrict__ h, const float* __restrict__ W,
                      const float* __restrict__ b, float* __restrict__ out) {
    __shared__ float Ws[512];
    int tid = threadIdx.x;
    Ws[tid] = W[tid];
    Ws[tid + 256] = W[tid + 256];
    __syncthreads();
    int w = (blockIdx.x * blockDim.x + tid) >> 5;
    if (w >= NN) return;
    int lane = tid & 31;
    const float4* hv = (const float4*)(h + (size_t)w * 256);
    float a0 = 0.f, a1 = 0.f;
#pragma unroll
    for (int v = 0; v < 2; v++) {
        float4 t = hv[v * 32 + lane];
        int k = (v * 32 + lane) * 4;
        a0 += t.x * Ws[(k + 0) * 2] + t.y * Ws[(k + 1) * 2] + t.z * Ws[(k + 2) * 2] + t.w * Ws[(k + 3) * 2];
        a1 += t.x * Ws[(k + 0) * 2 + 1] + t.y * Ws[(k + 1) * 2 + 1] + t.z * Ws[(k + 2) * 2 + 1] + t.w * Ws[(k + 3) * 2 + 1];
    }
#pragma unroll
    for (int off = 16; off > 0; off >>= 1) {
        a0 += __shfl_down_sync(0xffffffffu, a0, off);
        a1 += __shfl_down_sync(0xffffffffu, a1, off);
    }
    if (lane == 0) {
        out[(size_t)w * 2 + 0] = a0 + b[0];
        out[(size_t)w * 2 + 1] = a1 + b[1];
    }
}

// ---------------- host ----------------
extern "C" void kernel_launch(void* const* d_in, const int* in_sizes, int n_in,
                              void* d_out, int out_size) {
    const float* x = (const float*)d_in[0];
    const int* ei = (const int*)d_in[1];
    const float* outW = (const float*)d_in[26];
    const float* outB = (const float*)d_in[27];
    auto L = [&](int l, int p) { return (const float*)d_in[2 + l * 8 + p]; };

    float *z0, *z1, *hb;
    cudaGetSymbolAddress((void**)&z0, g_z0);
    cudaGetSymbolAddress((void**)&z1, g_z1);
    cudaGetSymbolAddress((void**)&hb, g_hb);
    float *sp, *tp;
    cudaGetSymbolAddress((void**)&sp, g_s);
    cudaGetSymbolAddress((void**)&tp, g_t);

    cudaFuncSetAttribute(k_mgemm, cudaFuncAttributeMaxDynamicSharedMemorySize, SM_BYTES);

    // CSR build (histogram over DST row = ei + NE)
    k_zero_deg<<<(NN + 255) / 256, 256>>>();
    k_count<<<(NE + 255) / 256, 256>>>(ei + NE);
    k_scan<<<1, 1024>>>();
    k_init_cursor<<<(NN + 255) / 256, 256>>>();
    k_fill<<<(NE + 255) / 256, 256>>>(ei);

    int aggBlocks = (NN + 7) / 8;
    dim3 gg((NN + 127) / 128, 2);  // 782 x 2

    // Layer 1 (F=128)
    k_agg<128><<<aggBlocks, 256>>>(x, z0);
    k_bnfold<<<1, 256>>>(L(0, 2), L(0, 3), L(0, 4), L(0, 5), L(0, 1));
    k_wconv<<<128, 256>>>(L(0, 0));
    k_mgemm<<<gg, 256, SM_BYTES>>>(z0, z1, NN, 128, sp, tp, 0);
    k_wconv<<<256, 256>>>(L(0, 6));
    k_mgemm<<<gg, 256, SM_BYTES>>>(z1, hb, NN, 256, nullptr, L(0, 7), 1);

    // Layer 2
    k_agg<256><<<aggBlocks, 256>>>(hb, z0);
    k_bnfold<<<1, 256>>>(L(1, 2), L(1, 3), L(1, 4), L(1, 5), L(1, 1));
    k_wconv<<<256, 256>>>(L(1, 0));
    k_mgemm<<<gg, 256, SM_BYTES>>>(z0, z1, NN, 256, sp, tp, 0);
    k_wconv<<<256, 256>>>(L(1, 6));
    k_mgemm<<<gg, 256, SM_BYTES>>>(z1, hb, NN, 256, nullptr, L(1, 7), 1);

    // Layer 3 (no final relu)
    k_agg<256><<<aggBlocks, 256>>>(hb, z0);
    k_bnfold<<<1, 256>>>(L(2, 2), L(2, 3), L(2, 4), L(2, 5), L(2, 1));
    k_wconv<<<256, 256>>>(L(2, 0));
    k_mgemm<<<gg, 256, SM_BYTES>>>(z0, z1, NN, 256, sp, tp, 0);
    k_wconv<<<256, 256>>>(L(2, 6));
    k_mgemm<<<gg, 256, SM_BYTES>>>(z1, hb, NN, 256, nullptr, L(2, 7), 2);

    // Output projection
    k_out<<<aggBlocks, 256>>>(hb, outW, outB, (float*)d_out);
}

// round 8
// speedup vs baseline: 1.4552x; 1.3331x over previous
#include <cuda_runtime.h>
#include <cuda_bf16.h>
#include <mma.h>
#include <cstdint>
#include <cstddef>

using namespace nvcuda;

#define NN 100000
#define NE 3200000
#define HD 256

// ---------------- device scratch ----------------
__device__ int   g_rowptr[NN + 1];
__device__ int   g_cursor[NN];
__device__ int   g_col[NE];
__device__ float g_z0[(size_t)NN * HD];
__device__ float g_z1[(size_t)NN * HD];
__device__ float g_hb[(size_t)NN * HD];
__device__ float g_s[3 * HD];
__device__ float g_t[3 * HD];
__device__ float g_wc[514];                 // fused W2@outW [256x2] + bias[2]
// bf16 weight images, row-major [K][256], 5 images (L0W1,L0W2,L1W1,L1W2,L2W1)
__device__ __nv_bfloat16 g_wh[5 * 256 * 256];
__device__ __nv_bfloat16 g_wl[5 * 256 * 256];

// ---------------- async-copy helpers ----------------
__device__ __forceinline__ uint32_t smem_cast(const void* p) {
    return (uint32_t)__cvta_generic_to_shared(p);
}
#define CP16(d, s) asm volatile("cp.async.ca.shared.global [%0], [%1], 16;" :: "r"(d), "l"(s))
#define CP_COMMIT() asm volatile("cp.async.commit_group;" ::: "memory")
#define CP_WAIT0() asm volatile("cp.async.wait_group 0;" ::: "memory")

// ---------------- CSR build ----------------
__global__ void k_count(const int* __restrict__ dst) {
    int e = blockIdx.x * blockDim.x + threadIdx.x;
    if (e < NE) atomicAdd(&g_cursor[dst[e]], 1);
}
// exclusive scan; writes rowptr[i+1]=incl and cursor[i]=excl
__global__ void k_scan() {
    __shared__ int wsum[32];
    __shared__ int s_carry;
    int tid = threadIdx.x, lane = tid & 31, wid = tid >> 5;
    if (tid == 0) s_carry = 0;
    __syncthreads();
    for (int base = 0; base < NN; base += 1024) {
        int i = base + tid;
        int v = (i < NN) ? g_cursor[i] : 0;
        int x = v;
#pragma unroll
        for (int off = 1; off < 32; off <<= 1) {
            int y = __shfl_up_sync(0xffffffffu, x, off);
            if (lane >= off) x += y;
        }
        if (lane == 31) wsum[wid] = x;
        __syncthreads();
        if (wid == 0) {
            int w = wsum[lane];
#pragma unroll
            for (int off = 1; off < 32; off <<= 1) {
                int y = __shfl_up_sync(0xffffffffu, w, off);
                if (lane >= off) w += y;
            }
            wsum[lane] = w;
        }
        __syncthreads();
        int incl = x + (wid ? wsum[wid - 1] : 0) + s_carry;
        if (i < NN) {
            g_rowptr[i + 1] = incl;
            g_cursor[i] = incl - v;
        }
        __syncthreads();
        if (tid == 1023) s_carry = incl;
        __syncthreads();
    }
    if (tid == 0) g_rowptr[0] = 0;
}
__global__ void k_fill(const int* __restrict__ ei) {
    int e = blockIdx.x * blockDim.x + threadIdx.x;
    if (e < NE) {
        int s = ei[e];
        int d = ei[NE + e];
        int p = atomicAdd(&g_cursor[d], 1);
        g_col[p] = s;
    }
}

// ---------------- aggregation: warp per node ----------------
template <int F>
__global__ void k_agg(const float* __restrict__ h, float* __restrict__ out) {
    int w = (blockIdx.x * blockDim.x + threadIdx.x) >> 5;
    if (w >= NN) return;
    int lane = threadIdx.x & 31;
    constexpr int V = F / 128;
    const float4* hv = (const float4*)h;
    float4 acc[V];
#pragma unroll
    for (int v = 0; v < V; v++) acc[v] = hv[(size_t)w * (F / 4) + v * 32 + lane];
    int e = g_rowptr[w], end = g_rowptr[w + 1];
    for (; e + 1 < end; e += 2) {
        int s0 = g_col[e], s1 = g_col[e + 1];
        const float4* p0 = hv + (size_t)s0 * (F / 4);
        const float4* p1 = hv + (size_t)s1 * (F / 4);
        float4 t0[V], t1[V];
#pragma unroll
        for (int v = 0; v < V; v++) {
            t0[v] = __ldg(p0 + v * 32 + lane);
            t1[v] = __ldg(p1 + v * 32 + lane);
        }
#pragma unroll
        for (int v = 0; v < V; v++) {
            acc[v].x += t0[v].x + t1[v].x;
            acc[v].y += t0[v].y + t1[v].y;
            acc[v].z += t0[v].z + t1[v].z;
            acc[v].w += t0[v].w + t1[v].w;
        }
    }
    if (e < end) {
        int s0 = g_col[e];
        const float4* p0 = hv + (size_t)s0 * (F / 4);
#pragma unroll
        for (int v = 0; v < V; v++) {
            float4 t0 = __ldg(p0 + v * 32 + lane);
            acc[v].x += t0.x; acc[v].y += t0.y; acc[v].z += t0.z; acc[v].w += t0.w;
        }
    }
    float4* ov = (float4*)out;
#pragma unroll
    for (int v = 0; v < V; v++) ov[(size_t)w * (F / 4) + v * 32 + lane] = acc[v];
}

// ---------------- BN fold (per layer, offset off) ----------------
__global__ void k_bnfold(const float* __restrict__ g, const float* __restrict__ be,
                         const float* __restrict__ mu, const float* __restrict__ var,
                         const float* __restrict__ b1, int off) {
    int j = threadIdx.x;
    float s = g[j] * rsqrtf(var[j] + 1e-5f);
    g_s[off + j] = s;
    g_t[off + j] = (b1[j] - mu[j]) * s + be[j];
}

// ---------------- all weight conversions in one kernel ----------------
__global__ void k_wconv_all(const float* __restrict__ w0, const float* __restrict__ w1,
                            const float* __restrict__ w2, const float* __restrict__ w3,
                            const float* __restrict__ w4) {
    int widx = blockIdx.y;
    int k = blockIdx.x;
    int n = threadIdx.x;
    const float* W;
    int K = 256;
    switch (widx) {
        case 0: W = w0; K = 128; break;
        case 1: W = w1; break;
        case 2: W = w2; break;
        case 3: W = w3; break;
        default: W = w4; break;
    }
    if (k >= K) return;
    float v = W[k * 256 + n];
    __nv_bfloat16 h = __float2bfloat16(v);
    __nv_bfloat16 l = __float2bfloat16(v - __bfloat162float(h));
    size_t o = (size_t)widx * 65536 + k * 256 + n;
    g_wh[o] = h;
    g_wl[o] = l;
}

// ---------------- fused tail weights: Wc = W2 @ outW, bc = b2 @ outW + ob ----------------
__global__ void k_wc(const float* __restrict__ W2, const float* __restrict__ b2,
                     const float* __restrict__ oW, const float* __restrict__ ob) {
    int i = threadIdx.x;
    float a0 = 0.f, a1 = 0.f;
    for (int d = 0; d < 256; d++) {
        float w = W2[i * 256 + d];
        a0 += w * oW[2 * d];
        a1 += w * oW[2 * d + 1];
    }
    g_wc[2 * i] = a0;
    g_wc[2 * i + 1] = a1;
    if (i < 2) {
        float b = 0.f;
        for (int d = 0; d < 256; d++) b += b2[d] * oW[2 * d + i];
        g_wc[512 + i] = b + ob[i];
    }
}

// ---------------- double-buffered wmma split-bf16 GEMM ----------------
// CTA tile 128x128, grid (ceil(M/128), 2), 8 warps 4x2 (warp 32x64), K-chunk 32.
#define ALD 40
#define BLD 136
#define A_IMG (128 * ALD * 2)                 // 10240 B per image
#define B_IMG (32 * BLD * 2)                  // 8704 B per image
#define BUF_BYTES (2 * A_IMG + 2 * B_IMG)     // 37888
#define SM_BYTES (2 * BUF_BYTES)              // 75776 (C tile 69632 overlays)

__global__ __launch_bounds__(256, 2) void k_mgemm(
    const float* __restrict__ A, float* __restrict__ C, int M, int K,
    const float* __restrict__ sc, const float* __restrict__ sh, int mode, int widx) {
    extern __shared__ char sm[];
    float* Cs = (float*)sm;
    int tid = threadIdx.x, wid = tid >> 5;
    int bm = blockIdx.x, bn = blockIdx.y;
    int moff = (wid & 3) * 32, noff = (wid >> 2) * 64;
    const __nv_bfloat16* WH = g_wh + (size_t)widx * 65536;
    const __nv_bfloat16* WL = g_wl + (size_t)widx * 65536;

    wmma::fragment<wmma::accumulator, 16, 16, 16, float> acc[2][4];
#pragma unroll
    for (int mf = 0; mf < 2; mf++)
#pragma unroll
        for (int nf = 0; nf < 4; nf++) wmma::fill_fragment(acc[mf][nf], 0.0f);

    const int nch = K >> 5;

    auto issueB = [&](int kt, int b) {
        char* BH = sm + b * BUF_BYTES + 2 * A_IMG;
        char* BL = BH + B_IMG;
#pragma unroll
        for (int i = 0; i < 2; i++) {
            int j = tid + i * 256;
            int r = j >> 4, cc = (j & 15) * 8;
            const __nv_bfloat16* sH = WH + (size_t)(kt + r) * 256 + bn * 128 + cc;
            const __nv_bfloat16* sL = WL + (size_t)(kt + r) * 256 + bn * 128 + cc;
            CP16(smem_cast(BH + (r * BLD + cc) * 2), sH);
            CP16(smem_cast(BL + (r * BLD + cc) * 2), sL);
        }
    };
    auto ldgA = [&](int kt, float4* v) {
#pragma unroll
        for (int i = 0; i < 4; i++) {
            int f = tid + i * 256;
            int row = f >> 3, k0 = (f & 7) * 4;
            int rg = bm * 128 + row;
            v[i] = (rg < M) ? *(const float4*)(A + (size_t)rg * K + kt + k0)
                            : make_float4(0.f, 0.f, 0.f, 0.f);
        }
    };
    auto stsA = [&](const float4* v, int b) {
        char* AH = sm + b * BUF_BYTES;
        char* AL = AH + A_IMG;
#pragma unroll
        for (int i = 0; i < 4; i++) {
            int f = tid + i * 256;
            int row = f >> 3, k0 = (f & 7) * 4;
            float av[4] = {v[i].x, v[i].y, v[i].z, v[i].w};
            uint32_t hp[2], lp[2];
#pragma unroll
            for (int p = 0; p < 2; p++) {
                __nv_bfloat16 h0 = __float2bfloat16(av[2 * p]);
                __nv_bfloat16 h1 = __float2bfloat16(av[2 * p + 1]);
                __nv_bfloat16 l0 = __float2bfloat16(av[2 * p] - __bfloat162float(h0));
                __nv_bfloat16 l1 = __float2bfloat16(av[2 * p + 1] - __bfloat162float(h1));
                hp[p] = (uint32_t)__bfloat16_as_ushort(h0) | ((uint32_t)__bfloat16_as_ushort(h1) << 16);
                lp[p] = (uint32_t)__bfloat16_as_ushort(l0) | ((uint32_t)__bfloat16_as_ushort(l1) << 16);
            }
            int el = row * ALD + k0;
            *(uint2*)(AH + 2 * el) = make_uint2(hp[0], hp[1]);
            *(uint2*)(AL + 2 * el) = make_uint2(lp[0], lp[1]);
        }
    };
    auto compute = [&](int b) {
        const __nv_bfloat16* AH = (const __nv_bfloat16*)(sm + b * BUF_BYTES);
        const __nv_bfloat16* AL = AH + A_IMG / 2;
        const __nv_bfloat16* BH = (const __nv_bfloat16*)(sm + b * BUF_BYTES + 2 * A_IMG);
        const __nv_bfloat16* BL = BH + B_IMG / 2;
#pragma unroll
        for (int kk = 0; kk < 32; kk += 16) {
            wmma::fragment<wmma::matrix_a, 16, 16, 16, __nv_bfloat16, wmma::row_major> ah[2], al2[2];
#pragma unroll
            for (int mf = 0; mf < 2; mf++) {
                wmma::load_matrix_sync(ah[mf], AH + (moff + mf * 16) * ALD + kk, ALD);
                wmma::load_matrix_sync(al2[mf], AL + (moff + mf * 16) * ALD + kk, ALD);
            }
#pragma unroll
            for (int nf = 0; nf < 4; nf++) {
                wmma::fragment<wmma::matrix_b, 16, 16, 16, __nv_bfloat16, wmma::row_major> bh, bl;
                wmma::load_matrix_sync(bh, BH + kk * BLD + noff + nf * 16, BLD);
                wmma::load_matrix_sync(bl, BL + kk * BLD + noff + nf * 16, BLD);
#pragma unroll
                for (int mf = 0; mf < 2; mf++) {
                    wmma::mma_sync(acc[mf][nf], ah[mf], bh, acc[mf][nf]);
                    wmma::mma_sync(acc[mf][nf], ah[mf], bl, acc[mf][nf]);
                    wmma::mma_sync(acc[mf][nf], al2[mf], bh, acc[mf][nf]);
                }
            }
        }
    };

    // prologue: chunk 0 -> buffer 0
    float4 st[4];
    ldgA(0, st);
    issueB(0, 0);
    stsA(st, 0);
    CP_COMMIT();

    for (int kc = 0; kc < nch; kc++) {
        CP_WAIT0();
        __syncthreads();
        bool nxt = (kc + 1 < nch);
        if (nxt) {
            ldgA((kc + 1) * 32, st);          // LDG latency hidden behind mma
            issueB((kc + 1) * 32, (kc + 1) & 1);
        }
        compute(kc & 1);
        if (nxt) {
            stsA(st, (kc + 1) & 1);
            CP_COMMIT();
        }
    }

    __syncthreads();
#pragma unroll
    for (int mf = 0; mf < 2; mf++)
#pragma unroll
        for (int nf = 0; nf < 4; nf++)
            wmma::store_matrix_sync(Cs + (moff + mf * 16) * BLD + noff + nf * 16,
                                    acc[mf][nf], BLD, wmma::mem_row_major);
    __syncthreads();

    // write out with fused BN/bias/ReLU. mode 0: relu(v*sc+sh); 1: relu(v+sh); 2: v+sh
    int row = tid >> 1;
    int cs = (tid & 1) * 64;
    int rg = bm * 128 + row;
    if (rg < M) {
#pragma unroll
        for (int q = 0; q < 16; q++) {
            int c = cs + q * 4;
            float4 v = *(float4*)(Cs + row * BLD + c);
            int gc = bn * 128 + c;
            float o[4] = {v.x, v.y, v.z, v.w};
#pragma unroll
            for (int j = 0; j < 4; j++) {
                float r;
                if (mode == 0) r = o[j] * __ldg(sc + gc + j) + __ldg(sh + gc + j);
                else r = o[j] + __ldg(sh + gc + j);
                if (mode != 2) r = fmaxf(r, 0.f);
                o[j] = r;
            }
            *(float4*)(C + (size_t)rg * 256 + gc) = make_float4(o[0], o[1], o[2], o[3]);
        }
    }
}

// ---------------- final projection (fused tail): out = h @ Wc + bc ----------------
__global__ void k_out(const float* __restrict__ h, const float* __restrict__ W,
                      const float* __restrict__ b, float* __restrict__ out) {
    __shared__ float Ws[512];
    int tid = threadIdx.x;
    Ws[tid] = W[tid];
    Ws[tid + 256] = W[tid + 256];
    __syncthreads();
    int w = (blockIdx.x * blockDim.x + tid) >> 5;
    if (w >= NN) return;
    int lane = tid & 31;
    const float4* hv = (const float4*)(h + (size_t)w * 256);
    float a0 = 0.f, a1 = 0.f;
#pragma unroll
    for (int v = 0; v < 2; v++) {
        float4 t = hv[v * 32 + lane];
        int k = (v * 32 + lane) * 4;
        a0 += t.x * Ws[(k + 0) * 2] + t.y * Ws[(k + 1) * 2] + t.z * Ws[(k + 2) * 2] + t.w * Ws[(k + 3) * 2];
        a1 += t.x * Ws[(k + 0) * 2 + 1] + t.y * Ws[(k + 1) * 2 + 1] + t.z * Ws[(k + 2) * 2 + 1] + t.w * Ws[(k + 3) * 2 + 1];
    }
#pragma unroll
    for (int off = 16; off > 0; off >>= 1) {
        a0 += __shfl_down_sync(0xffffffffu, a0, off);
        a1 += __shfl_down_sync(0xffffffffu, a1, off);
    }
    if (lane == 0) {
        out[(size_t)w * 2 + 0] = a0 + b[0];
        out[(size_t)w * 2 + 1] = a1 + b[1];
    }
}

// ---------------- host ----------------
extern "C" void kernel_launch(void* const* d_in, const int* in_sizes, int n_in,
                              void* d_out, int out_size) {
    const float* x = (const float*)d_in[0];
    const int* ei = (const int*)d_in[1];
    const float* outW = (const float*)d_in[26];
    const float* outB = (const float*)d_in[27];
    auto L = [&](int l, int p) { return (const float*)d_in[2 + l * 8 + p]; };

    float *z0, *z1, *hb, *sp, *tp, *wc;
    int* cur;
    cudaGetSymbolAddress((void**)&z0, g_z0);
    cudaGetSymbolAddress((void**)&z1, g_z1);
    cudaGetSymbolAddress((void**)&hb, g_hb);
    cudaGetSymbolAddress((void**)&sp, g_s);
    cudaGetSymbolAddress((void**)&tp, g_t);
    cudaGetSymbolAddress((void**)&wc, g_wc);
    cudaGetSymbolAddress((void**)&cur, g_cursor);

    cudaFuncSetAttribute(k_mgemm, cudaFuncAttributeMaxDynamicSharedMemorySize, SM_BYTES);

    // ---- CSR build ----
    cudaMemsetAsync(cur, 0, NN * sizeof(int));
    k_count<<<(NE + 255) / 256, 256>>>(ei + NE);
    k_scan<<<1, 1024>>>();
    k_fill<<<(NE + 255) / 256, 256>>>(ei);

    int aggBlocks = (NN + 7) / 8;
    dim3 gg((NN + 127) / 128, 2);

    // first aggregation early (profiler slot), then parameter prep
    k_agg<128><<<aggBlocks, 256>>>(x, z0);
    k_wconv_all<<<dim3(256, 5), 256>>>(L(0, 0), L(0, 6), L(1, 0), L(1, 6), L(2, 0));
    k_bnfold<<<1, 256>>>(L(0, 2), L(0, 3), L(0, 4), L(0, 5), L(0, 1), 0);
    k_bnfold<<<1, 256>>>(L(1, 2), L(1, 3), L(1, 4), L(1, 5), L(1, 1), 256);
    k_bnfold<<<1, 256>>>(L(2, 2), L(2, 3), L(2, 4), L(2, 5), L(2, 1), 512);
    k_wc<<<1, 256>>>(L(2, 6), L(2, 7), outW, outB);

    // Layer 1
    k_mgemm<<<gg, 256, SM_BYTES>>>(z0, z1, NN, 128, sp, tp, 0, 0);
    k_mgemm<<<gg, 256, SM_BYTES>>>(z1, hb, NN, 256, nullptr, L(0, 7), 1, 1);

    // Layer 2
    k_agg<256><<<aggBlocks, 256>>>(hb, z0);
    k_mgemm<<<gg, 256, SM_BYTES>>>(z0, z1, NN, 256, sp + 256, tp + 256, 0, 2);
    k_mgemm<<<gg, 256, SM_BYTES>>>(z1, hb, NN, 256, nullptr, L(1, 7), 1, 3);

    // Layer 3 first GEMM, then fused tail (W2@outW folded)
    k_agg<256><<<aggBlocks, 256>>>(hb, z0);
    k_mgemm<<<gg, 256, SM_BYTES>>>(z0, z1, NN, 256, sp + 512, tp + 512, 0, 4);
    k_out<<<aggBlocks, 256>>>(z1, wc, wc + 512, (float*)d_out);
}